// round 14
// baseline (speedup 1.0000x reference)
#include <cuda_runtime.h>
#include <cuda_fp16.h>
#include <math.h>
#include <stdint.h>

#define Bc 32
#define Lc 4096
#define Cc 64
#define Dc 128
#define Kc 2048
#define SEL_BLOCKS 32
#define SP_BLOCKS 256    // sparse blocks: 4 tiles x 64 rows each, 8 per batch
#define FULL_BLOCKS 2048 // full tiles of 64 rows

// ---------------- scratch (device globals; no allocs) -----------------------
__device__ float g_scores[Bc * Lc];
__device__ int   g_idx   [Bc * Kc];
__device__ float g_part  [Bc * 8 * Dc];   // one partial per sparse block
__device__ float g_agg   [Bc * Dc];
__device__ int   g_cnt   [Bc];
__device__ int   g_flag  [Bc];
__device__ int   g_iflag [Bc];
// B fragments (fp16, single term) in mma layout: [kt][nt][lane][reg] u32
__device__ __align__(16) uint32_t g_bff[4 * 16 * 32 * 2];  // full_w
__device__ __align__(16) uint32_t g_bfs[4 * 16 * 32 * 2];  // sparse_w

// ---------------- helpers ---------------------------------------------------
__device__ __forceinline__ uint32_t smem_u32(const void* p) {
    uint32_t a;
    asm("{ .reg .u64 t; cvta.to.shared.u64 t, %1; cvt.u32.u64 %0, t; }"
        : "=r"(a) : "l"(p));
    return a;
}
__device__ __forceinline__ uint32_t h2u(__half2 h) {
    return *reinterpret_cast<uint32_t*>(&h);
}
__device__ __forceinline__ void ldmatrix4(uint32_t* a, uint32_t addr) {
    asm volatile("ldmatrix.sync.aligned.m8n8.x4.shared.b16 {%0,%1,%2,%3}, [%4];"
                 : "=r"(a[0]), "=r"(a[1]), "=r"(a[2]), "=r"(a[3]) : "r"(addr));
}
__device__ __forceinline__ void mma16816(float* c, const uint32_t* a,
                                         const uint32_t* b) {
    asm volatile(
        "mma.sync.aligned.m16n8k16.row.col.f32.f16.f16.f32 "
        "{%0,%1,%2,%3}, {%4,%5,%6,%7}, {%8,%9}, {%0,%1,%2,%3};"
        : "+f"(c[0]), "+f"(c[1]), "+f"(c[2]), "+f"(c[3])
        : "r"(a[0]), "r"(a[1]), "r"(a[2]), "r"(a[3]), "r"(b[0]), "r"(b[1]));
}
__device__ __forceinline__ float gelu_f(float p) {
    float u = 1.5957691216f * p * (1.f + 0.044715f * p * p);
    u = fminf(u, 15.f);
    float e = __expf(u);
    return p * e / (e + 1.f);
}

// dynamic smem layout (bytes) — 64-row tiles
#define SM_IDX   0        // 64 ints
#define SM_SPC   256      // 2*128 f32
#define SM_RED   1280     // 64*4 float2 = 2048
#define SM_MUI   3328     // 64 float2 = 512
#define SM_AH    3840     // 64 rows * 144B = 9216
#define SM_AL    13056    // 9216
#define A_STRIDE 144
// select-role aliases (select blocks never touch A tiles)
#define SM_KEYS  3840     // 4096 u32 = 16384
#define SM_HIST  20224    // 8*256*4 = 8192
#define SM_TOT   28416    // 256*4 = 1024
#define SM_TOTAL 29440

// ---------------------------------------------------------------------------
// setup helper: fp16 B fragments in mma register layout (entry e in [0,4096))
// ---------------------------------------------------------------------------
__device__ __forceinline__ void setup_entry(int e, const float* __restrict__ spw,
                                            const float* __restrict__ fw)
{
    int reg  = e & 1;
    int lane = (e >> 1) & 31;
    int nt   = (e >> 6) & 15;
    int kt   = (e >> 10) & 3;
    int n = nt * 8 + (lane >> 2);
    int k = kt * 16 + reg * 8 + (lane & 3) * 2;
    g_bff[e] = h2u(__floats2half2_rn(fw[k * Dc + n],  fw[(k + 1) * Dc + n]));
    g_bfs[e] = h2u(__floats2half2_rn(spw[k * Dc + n], spw[(k + 1) * Dc + n]));
}

// ---------------------------------------------------------------------------
// 1. scores: 8 threads/row, float4 loads (+ setup & flag reset in low blocks)
// ---------------------------------------------------------------------------
__global__ void scores_kernel(const float* __restrict__ x,
                              const float* __restrict__ sw,
                              const float* __restrict__ sb,
                              const float* __restrict__ spw,
                              const float* __restrict__ fw)
{
    int tid = threadIdx.x;
    if (blockIdx.x < 4) {
        int e0 = blockIdx.x * 1024 + tid;
        #pragma unroll
        for (int j = 0; j < 4; j++) setup_entry(e0 + j * 256, spw, fw);
    }
    if (blockIdx.x == 4 && tid < Bc) {
        g_cnt[tid] = 0; g_flag[tid] = 0; g_iflag[tid] = 0;
    }

    int row = blockIdx.x * 32 + (tid >> 3);   // grid = B*L/32 = 4096
    int j   = tid & 7;
    const float4* xr = (const float4*)(x + (size_t)row * Cc + j * 8);
    float4 a = xr[0], c = xr[1];
    const float4* wp = (const float4*)(sw + j * 8);
    float4 w0 = wp[0], w1 = wp[1];
    float s = a.x*w0.x + a.y*w0.y + a.z*w0.z + a.w*w0.w
            + c.x*w1.x + c.y*w1.y + c.z*w1.z + c.w*w1.w;
    s += __shfl_xor_sync(0xffffffffu, s, 1);
    s += __shfl_xor_sync(0xffffffffu, s, 2);
    s += __shfl_xor_sync(0xffffffffu, s, 4);
    if (j == 0) g_scores[row] = s + sb[0];
}

// ---------------------------------------------------------------------------
// convert 64 x-rows (f32) -> split fp16 A tiles in smem. 256 threads.
// ---------------------------------------------------------------------------
__device__ __forceinline__ void convert_a(char* smem, const float* __restrict__ xbase,
                                          const int* rowSrc, long rowBase, int tid)
{
    #pragma unroll
    for (int it = 0; it < 4; it++) {
        int idx4 = it * 256 + tid;          // 1024 float4 = 64 rows x 16
        int row  = idx4 >> 4;
        int k4   = idx4 & 15;
        long gr  = rowSrc ? (long)rowSrc[row] : (rowBase + row);
        float4 v = *(const float4*)(xbase + gr * Cc + k4 * 4);
        __half2 h01 = __floats2half2_rn(v.x, v.y);
        __half2 h23 = __floats2half2_rn(v.z, v.w);
        __half2 l01 = __floats2half2_rn(v.x - __low2float(h01),
                                        v.y - __high2float(h01));
        __half2 l23 = __floats2half2_rn(v.z - __low2float(h23),
                                        v.w - __high2float(h23));
        int off = row * A_STRIDE + k4 * 8;
        *(uint2*)(smem + SM_AH + off) = make_uint2(h2u(h01), h2u(h23));
        *(uint2*)(smem + SM_AL + off) = make_uint2(h2u(l01), h2u(l23));
    }
}

// ---------------------------------------------------------------------------
// warp GEMM (fp16 2-term): rows [mrow,mrow+32) x cols [nw*32,nw*32+32)
// ---------------------------------------------------------------------------
__device__ __forceinline__ void warp_gemm(float acc[2][4][4], uint32_t sbase,
                                          const uint32_t* __restrict__ bfrag,
                                          int mrow, int nw, int lane)
{
    int rowl   = lane & 15;
    int coloff = (lane >= 16) ? 16 : 0;

    uint32_t bh[2][4][2];
    #pragma unroll
    for (int nt = 0; nt < 4; nt++) {
        uint2 h = *(const uint2*)(bfrag + ((0 * 16 + (nw * 4 + nt)) * 32 + lane) * 2);
        bh[0][nt][0] = h.x; bh[0][nt][1] = h.y;
    }
    #pragma unroll
    for (int kt = 0; kt < 4; kt++) {
        int cur = kt & 1, nxt = cur ^ 1;
        if (kt < 3) {
            #pragma unroll
            for (int nt = 0; nt < 4; nt++) {
                uint2 h = *(const uint2*)(bfrag + (((kt + 1) * 16 + (nw * 4 + nt)) * 32 + lane) * 2);
                bh[nxt][nt][0] = h.x; bh[nxt][nt][1] = h.y;
            }
        }
        #pragma unroll
        for (int mt = 0; mt < 2; mt++) {
            uint32_t ah[4], al[4];
            uint32_t aoff = (mrow + mt * 16 + rowl) * A_STRIDE + kt * 32 + coloff;
            ldmatrix4(ah, sbase + SM_AH + aoff);
            ldmatrix4(al, sbase + SM_AL + aoff);
            #pragma unroll
            for (int nt = 0; nt < 4; nt++) mma16816(acc[mt][nt], ah, bh[cur][nt]);
            #pragma unroll
            for (int nt = 0; nt < 4; nt++) mma16816(acc[mt][nt], al, bh[cur][nt]);
        }
    }
}

// ---------------------------------------------------------------------------
// select device routine (256 threads, 8 warps): radix select + compaction
// ---------------------------------------------------------------------------
__device__ void do_select(char* smem, int b, int tid)
{
    unsigned* keys = (unsigned*)(smem + SM_KEYS);
    int*      hist = (int*)(smem + SM_HIST);     // [8][256]
    int*      total = (int*)(smem + SM_TOT);
    __shared__ unsigned s_prefix;
    __shared__ int s_rem, s_budget;
    __shared__ int wGt[8], wEq[8], preSel[8], preEq[8];

    int wid = tid >> 5, lane = tid & 31;

    for (int i = tid; i < Lc; i += 256) {
        unsigned u = __float_as_uint(g_scores[b * Lc + i]);
        keys[i] = u ^ (((unsigned)((int)u >> 31)) | 0x80000000u);
    }
    if (tid == 0) { s_prefix = 0u; s_rem = Kc; }
    __syncthreads();

    for (int shift = 24; shift >= 0; shift -= 8) {
        unsigned maskHigh = (shift == 24) ? 0u : (0xFFFFFFFFu << (shift + 8));
        #pragma unroll
        for (int j = 0; j < 8; j++) hist[j * 256 + tid] = 0;
        __syncthreads();
        unsigned prefix = s_prefix;
        #pragma unroll
        for (int c = 0; c < 16; c++) {
            unsigned k = keys[c * 256 + tid];
            if ((k & maskHigh) == prefix) {
                int bin = (k >> shift) & 255;
                unsigned mm  = __activemask();
                unsigned grp = __match_any_sync(mm, bin);
                if (lane == (__ffs(grp) - 1)) atomicAdd(&hist[wid * 256 + bin], __popc(grp));
            }
        }
        __syncthreads();
        {
            int c = 0;
            #pragma unroll
            for (int w = 0; w < 8; w++) c += hist[w * 256 + tid];
            total[tid] = c;
        }
        __syncthreads();
        if (wid == 0) {
            int base = lane * 8;
            int lsum = 0;
            #pragma unroll
            for (int j = 0; j < 8; j++) lsum += total[base + j];
            int v = lsum;
            #pragma unroll
            for (int off = 1; off < 32; off <<= 1) {
                int t = __shfl_down_sync(0xffffffffu, v, off);
                if (lane + off < 32) v += t;
            }
            int suf = v - lsum;
            int rem = s_rem;
            int running = suf;
            #pragma unroll
            for (int j = 7; j >= 0; j--) {
                int bin = base + j;
                int c = total[bin];
                if (running < rem && running + c >= rem) {
                    s_prefix = prefix | ((unsigned)bin << shift);
                    s_rem = rem - running;
                }
                running += c;
            }
        }
        __syncthreads();
    }
    unsigned T = s_prefix;

    int gtc = 0, eqc = 0;
    #pragma unroll
    for (int c = 0; c < 16; c++) {
        unsigned k = keys[wid * 512 + c * 32 + lane];
        gtc += (k > T); eqc += (k == T);
    }
    #pragma unroll
    for (int off = 16; off; off >>= 1) {
        gtc += __shfl_xor_sync(0xffffffffu, gtc, off);
        eqc += __shfl_xor_sync(0xffffffffu, eqc, off);
    }
    if (lane == 0) { wGt[wid] = gtc; wEq[wid] = eqc; }
    __syncthreads();
    if (tid == 0) {
        int totGt = 0;
        #pragma unroll
        for (int w = 0; w < 8; w++) totGt += wGt[w];
        int budget = Kc - totGt;
        int runSel = 0, runEq = 0;
        #pragma unroll
        for (int w = 0; w < 8; w++) {
            preSel[w] = runSel; preEq[w] = runEq;
            int eqSel = budget - runEq;
            if (eqSel < 0) eqSel = 0;
            if (eqSel > wEq[w]) eqSel = wEq[w];
            runSel += wGt[w] + eqSel;
            runEq  += wEq[w];
        }
        s_budget = budget;
    }
    __syncthreads();
    int budget = s_budget;
    int selOff = preSel[wid], eqOff = preEq[wid];
    unsigned below = (1u << lane) - 1u;
    #pragma unroll
    for (int c = 0; c < 16; c++) {
        int i = wid * 512 + c * 32 + lane;
        unsigned k = keys[i];
        bool isGt = (k > T), isEq = (k == T);
        unsigned balEq = __ballot_sync(0xffffffffu, isEq);
        int eqRank = eqOff + __popc(balEq & below);
        bool sel = isGt || (isEq && eqRank < budget);
        unsigned balSel = __ballot_sync(0xffffffffu, sel);
        int pos = selOff + __popc(balSel & below);
        if (sel) g_idx[b * Kc + pos] = i;
        selOff += __popc(balSel);
        eqOff  += __popc(balEq);
    }

    __threadfence();
    __syncthreads();
    if (tid == 0) atomicExch(&g_iflag[b], 1);
}

// ---------------------------------------------------------------------------
// 2. fused: [0,32) select | [32,288) sparse (4x64-row tiles) | [288,2336) full
// ---------------------------------------------------------------------------
__global__ void __launch_bounds__(256, 3)
fused_mma(const float* __restrict__ x,  const float* __restrict__ spb,
          const float* __restrict__ fb, const float* __restrict__ lg,
          const float* __restrict__ lb, float* __restrict__ out)
{
    extern __shared__ char smem[];
    uint32_t sb = smem_u32(smem);
    int tid = threadIdx.x, warp = tid >> 5, lane = tid & 31;
    int nw = warp & 3, mg = warp >> 2, mrow = mg * 32;
    int cb = (lane & 3) * 2 + nw * 32;

    if (blockIdx.x < SEL_BLOCKS) {
        do_select(smem, blockIdx.x, tid);
        return;
    }

    if (blockIdx.x < SEL_BLOCKS + SP_BLOCKS) {
        // ------------------ sparse path: 4 gathered 64-row tiles -----------
        int bid = blockIdx.x - SEL_BLOCKS;
        int b = bid >> 3;                         // 8 blocks per batch
        const float* xb = x + (size_t)b * Lc * Cc;
        float* spc = (float*)(smem + SM_SPC);
        float partAcc = 0.f;                      // per-thread col partial

        if (tid == 0) {
            while (atomicAdd(&g_iflag[b], 0) == 0) __nanosleep(100);
            __threadfence();
        }
        __syncthreads();

        for (int j = 0; j < 4; j++) {
            int tile = (bid & 7) * 4 + j;         // 0..31
            if (tid < 64)
                ((int*)(smem + SM_IDX))[tid] = g_idx[b * Kc + tile * 64 + tid];
            __syncthreads();
            convert_a(smem, xb, (const int*)(smem + SM_IDX), 0, tid);
            __syncthreads();

            float acc[2][4][4];
            #pragma unroll
            for (int i = 0; i < 2; i++)
                #pragma unroll
                for (int q = 0; q < 4; q++)
                    #pragma unroll
                    for (int k = 0; k < 4; k++) acc[i][q][k] = 0.f;

            warp_gemm(acc, sb, g_bfs, mrow, nw, lane);

            #pragma unroll
            for (int nt = 0; nt < 4; nt++) {
                int c = cb + nt * 8;
                float b0 = spb[c], b1 = spb[c + 1];
                float p0 = gelu_f(acc[0][nt][0] + b0) + gelu_f(acc[0][nt][2] + b0)
                         + gelu_f(acc[1][nt][0] + b0) + gelu_f(acc[1][nt][2] + b0);
                float p1 = gelu_f(acc[0][nt][1] + b1) + gelu_f(acc[0][nt][3] + b1)
                         + gelu_f(acc[1][nt][1] + b1) + gelu_f(acc[1][nt][3] + b1);
                #pragma unroll
                for (int off = 4; off <= 16; off <<= 1) {
                    p0 += __shfl_xor_sync(0xffffffffu, p0, off);
                    p1 += __shfl_xor_sync(0xffffffffu, p1, off);
                }
                if (lane < 4)
                    *(float2*)&spc[mg * 128 + c] = make_float2(p0, p1);
            }
            __syncthreads();
            if (tid < 128) partAcc += spc[tid] + spc[128 + tid];
            __syncthreads();
        }
        if (tid < 128)
            g_part[(b * 8 + (bid & 7)) * Dc + tid] = partAcc;

        // last block of this batch: reduce partials -> mean, release flag
        __shared__ int s_last;
        __threadfence();
        __syncthreads();
        if (tid == 0) s_last = (atomicAdd(&g_cnt[b], 1) == 7);
        __syncthreads();
        if (s_last) {
            if (tid < 128) {
                float s = 0.f;
                #pragma unroll
                for (int t = 0; t < 8; t++)
                    s += g_part[(b * 8 + t) * Dc + tid];
                g_agg[b * Dc + tid] = s * (1.0f / (float)Kc);
            }
            __threadfence();
            __syncthreads();
            if (tid == 0) atomicExch(&g_flag[b], 1);
        }
    } else {
        // ------------------ full path: GEMM -> wait agg -> LN --------------
        int tile = blockIdx.x - SEL_BLOCKS - SP_BLOCKS;   // 0..2047
        int b = tile >> 6;                                // 64 tiles per batch
        long rowBase = (long)tile * 64;

        convert_a(smem, x, nullptr, rowBase, tid);
        __syncthreads();

        float acc[2][4][4];
        #pragma unroll
        for (int i = 0; i < 2; i++)
            #pragma unroll
            for (int q = 0; q < 4; q++)
                #pragma unroll
                for (int k = 0; k < 4; k++) acc[i][q][k] = 0.f;

        warp_gemm(acc, sb, g_bff, mrow, nw, lane);

        if (tid == 0) {
            while (atomicAdd(&g_flag[b], 0) == 0) __nanosleep(200);
            __threadfence();
        }
        __syncthreads();

        float gg[4][2], bb[4][2];
        #pragma unroll
        for (int nt = 0; nt < 4; nt++) {
            int c = cb + nt * 8;
            float b0 = fb[c]     + g_agg[b * Dc + c];
            float b1 = fb[c + 1] + g_agg[b * Dc + c + 1];
            gg[nt][0] = lg[c]; gg[nt][1] = lg[c + 1];
            bb[nt][0] = lb[c]; bb[nt][1] = lb[c + 1];
            #pragma unroll
            for (int mt = 0; mt < 2; mt++) {
                acc[mt][nt][0] += b0; acc[mt][nt][1] += b1;
                acc[mt][nt][2] += b0; acc[mt][nt][3] += b1;
            }
        }

        float2* red = (float2*)(smem + SM_RED);
        int r0 = lane >> 2;
        #pragma unroll
        for (int mt = 0; mt < 2; mt++) {
            #pragma unroll
            for (int h = 0; h < 2; h++) {
                float S = 0.f, Q = 0.f;
                #pragma unroll
                for (int nt = 0; nt < 4; nt++) {
                    float v0 = acc[mt][nt][2 * h], v1 = acc[mt][nt][2 * h + 1];
                    S += v0 + v1; Q += v0 * v0 + v1 * v1;
                }
                S += __shfl_xor_sync(0xffffffffu, S, 1);
                Q += __shfl_xor_sync(0xffffffffu, Q, 1);
                S += __shfl_xor_sync(0xffffffffu, S, 2);
                Q += __shfl_xor_sync(0xffffffffu, Q, 2);
                if ((lane & 3) == 0)
                    red[(mrow + mt * 16 + r0 + 8 * h) * 4 + nw] = make_float2(S, Q);
            }
        }
        __syncthreads();
        float2* mui = (float2*)(smem + SM_MUI);
        if (tid < 64) {
            float2 a = red[tid * 4], c1 = red[tid * 4 + 1],
                   c2 = red[tid * 4 + 2], c3 = red[tid * 4 + 3];
            float Sr = a.x + c1.x + c2.x + c3.x;
            float Qr = a.y + c1.y + c2.y + c3.y;
            const float invD = 1.0f / 128.0f;
            float mu  = Sr * invD;
            float var = Qr * invD - mu * mu;
            mui[tid] = make_float2(mu, rsqrtf(var + 1e-5f));
        }
        __syncthreads();

        #pragma unroll
        for (int mt = 0; mt < 2; mt++) {
            #pragma unroll
            for (int h = 0; h < 2; h++) {
                int row = mrow + mt * 16 + r0 + 8 * h;
                float2 mi = mui[row];
                float* op = out + (rowBase + row) * Dc;
                #pragma unroll
                for (int nt = 0; nt < 4; nt++) {
                    int c = cb + nt * 8;
                    float o0 = (acc[mt][nt][2*h]   - mi.x) * mi.y * gg[nt][0] + bb[nt][0];
                    float o1 = (acc[mt][nt][2*h+1] - mi.x) * mi.y * gg[nt][1] + bb[nt][1];
                    *(float2*)&op[c] = make_float2(o0, o1);
                }
            }
        }
    }
}

// ---------------------------------------------------------------------------
extern "C" void kernel_launch(void* const* d_in, const int* in_sizes, int n_in,
                              void* d_out, int out_size)
{
    const float* x   = (const float*)d_in[0];
    const float* sw  = (const float*)d_in[1];
    const float* sb  = (const float*)d_in[2];
    const float* spw = (const float*)d_in[3];
    const float* spb = (const float*)d_in[4];
    const float* fw  = (const float*)d_in[5];
    const float* fb  = (const float*)d_in[6];
    const float* lg  = (const float*)d_in[7];
    const float* lb  = (const float*)d_in[8];
    float* out = (float*)d_out;

    scores_kernel<<<(Bc * Lc) / 32, 256>>>(x, sw, sb, spw, fw);
    fused_mma<<<SEL_BLOCKS + SP_BLOCKS + FULL_BLOCKS, 256, SM_TOTAL>>>(
        x, spb, fb, lg, lb, out);
}

// round 15
// speedup vs baseline: 1.0013x; 1.0013x over previous
#include <cuda_runtime.h>
#include <cuda_fp16.h>
#include <math.h>
#include <stdint.h>

#define Bc 32
#define Lc 4096
#define Cc 64
#define Dc 128
#define Kc 2048
#define SEL_BLOCKS 32
#define SP_BLOCKS 256     // sparse persistent blocks: 4 x 64-row tiles each
#define FULL_PBLK 448     // full persistent blocks
#define FULL_TILES 2048   // 64-row tiles

// ---------------- scratch (device globals; no allocs) -----------------------
__device__ float g_scores[Bc * Lc];
__device__ int   g_idx   [Bc * Kc];
__device__ float g_part  [Bc * 8 * Dc];
__device__ float g_agg   [Bc * Dc];
__device__ int   g_cnt   [Bc];
__device__ int   g_flag  [Bc];
__device__ int   g_iflag [Bc];
// B fragments (fp16) in mma layout: [kt][nt][lane][reg] u32
__device__ __align__(16) uint32_t g_bff[4 * 16 * 32 * 2];  // full_w
__device__ __align__(16) uint32_t g_bfs[4 * 16 * 32 * 2];  // sparse_w

// ---------------- helpers ---------------------------------------------------
__device__ __forceinline__ uint32_t smem_u32(const void* p) {
    uint32_t a;
    asm("{ .reg .u64 t; cvta.to.shared.u64 t, %1; cvt.u32.u64 %0, t; }"
        : "=r"(a) : "l"(p));
    return a;
}
__device__ __forceinline__ uint32_t h2u(__half2 h) {
    return *reinterpret_cast<uint32_t*>(&h);
}
__device__ __forceinline__ void ldmatrix4(uint32_t* a, uint32_t addr) {
    asm volatile("ldmatrix.sync.aligned.m8n8.x4.shared.b16 {%0,%1,%2,%3}, [%4];"
                 : "=r"(a[0]), "=r"(a[1]), "=r"(a[2]), "=r"(a[3]) : "r"(addr));
}
__device__ __forceinline__ void mma16816(float* c, const uint32_t* a,
                                         const uint32_t* b) {
    asm volatile(
        "mma.sync.aligned.m16n8k16.row.col.f32.f16.f16.f32 "
        "{%0,%1,%2,%3}, {%4,%5,%6,%7}, {%8,%9}, {%0,%1,%2,%3};"
        : "+f"(c[0]), "+f"(c[1]), "+f"(c[2]), "+f"(c[3])
        : "r"(a[0]), "r"(a[1]), "r"(a[2]), "r"(a[3]), "r"(b[0]), "r"(b[1]));
}
__device__ __forceinline__ float gelu_f(float p) {
    float u = 1.5957691216f * p * (1.f + 0.044715f * p * p);
    u = fminf(u, 15.f);
    float e = __expf(u);
    return p * e / (e + 1.f);
}

// dynamic smem layout (bytes) — 64-row tiles, double-buffered A
#define SM_SPC   256      // 2*128 f32 (sparse)
#define SM_RED   1280     // 64*4 float2 = 2048
#define SM_MUI   3328     // 64 float2 = 512
#define SM_A0    3840     // hi 9216 + lo 9216 = 18432
#define SM_A1    22272
#define A_LOFF   9216
#define A_STRIDE 144
#define SM_TOTAL 40704
// select-role aliases (select blocks never touch A bufs)
#define SM_KEYS  3840     // 4096 u32 = 16384
#define SM_HIST  20224    // 8*256*4 = 8192
#define SM_TOT   28416    // 1024

// ---------------------------------------------------------------------------
// setup helper: fp16 B fragments in mma register layout (entry e in [0,4096))
// ---------------------------------------------------------------------------
__device__ __forceinline__ void setup_entry(int e, const float* __restrict__ spw,
                                            const float* __restrict__ fw)
{
    int reg  = e & 1;
    int lane = (e >> 1) & 31;
    int nt   = (e >> 6) & 15;
    int kt   = (e >> 10) & 3;
    int n = nt * 8 + (lane >> 2);
    int k = kt * 16 + reg * 8 + (lane & 3) * 2;
    g_bff[e] = h2u(__floats2half2_rn(fw[k * Dc + n],  fw[(k + 1) * Dc + n]));
    g_bfs[e] = h2u(__floats2half2_rn(spw[k * Dc + n], spw[(k + 1) * Dc + n]));
}

// ---------------------------------------------------------------------------
// 1. scores: 8 threads/row, float4 loads (+ setup & flag reset in low blocks)
// ---------------------------------------------------------------------------
__global__ void scores_kernel(const float* __restrict__ x,
                              const float* __restrict__ sw,
                              const float* __restrict__ sb,
                              const float* __restrict__ spw,
                              const float* __restrict__ fw)
{
    int tid = threadIdx.x;
    if (blockIdx.x < 4) {
        int e0 = blockIdx.x * 1024 + tid;
        #pragma unroll
        for (int j = 0; j < 4; j++) setup_entry(e0 + j * 256, spw, fw);
    }
    if (blockIdx.x == 4 && tid < Bc) {
        g_cnt[tid] = 0; g_flag[tid] = 0; g_iflag[tid] = 0;
    }

    int row = blockIdx.x * 32 + (tid >> 3);   // grid = B*L/32 = 4096
    int j   = tid & 7;
    const float4* xr = (const float4*)(x + (size_t)row * Cc + j * 8);
    float4 a = xr[0], c = xr[1];
    const float4* wp = (const float4*)(sw + j * 8);
    float4 w0 = wp[0], w1 = wp[1];
    float s = a.x*w0.x + a.y*w0.y + a.z*w0.z + a.w*w0.w
            + c.x*w1.x + c.y*w1.y + c.z*w1.z + c.w*w1.w;
    s += __shfl_xor_sync(0xffffffffu, s, 1);
    s += __shfl_xor_sync(0xffffffffu, s, 2);
    s += __shfl_xor_sync(0xffffffffu, s, 4);
    if (j == 0) g_scores[row] = s + sb[0];
}

// ---------------------------------------------------------------------------
// convert 64 x-rows (f32) -> split fp16 A tile at smem bufBase. 256 threads.
// rowSrc: global idx list (L1 broadcast) or null for contiguous rows
// ---------------------------------------------------------------------------
__device__ __forceinline__ void convert_a(char* smem, int bufBase,
                                          const float* __restrict__ xbase,
                                          const int* __restrict__ rowSrc,
                                          long rowBase, int tid)
{
    #pragma unroll
    for (int it = 0; it < 4; it++) {
        int idx4 = it * 256 + tid;          // 1024 float4 = 64 rows x 16
        int row  = idx4 >> 4;
        int k4   = idx4 & 15;
        long gr  = rowSrc ? (long)rowSrc[row] : (rowBase + row);
        float4 v = *(const float4*)(xbase + gr * Cc + k4 * 4);
        __half2 h01 = __floats2half2_rn(v.x, v.y);
        __half2 h23 = __floats2half2_rn(v.z, v.w);
        __half2 l01 = __floats2half2_rn(v.x - __low2float(h01),
                                        v.y - __high2float(h01));
        __half2 l23 = __floats2half2_rn(v.z - __low2float(h23),
                                        v.w - __high2float(h23));
        int off = bufBase + row * A_STRIDE + k4 * 8;
        *(uint2*)(smem + off)          = make_uint2(h2u(h01), h2u(h23));
        *(uint2*)(smem + off + A_LOFF) = make_uint2(h2u(l01), h2u(l23));
    }
}

// ---------------------------------------------------------------------------
// warp GEMM (fp16 2-term): rows [mrow,mrow+32) x cols [nw*32,nw*32+32)
// ahBase = absolute smem addr of hi plane; lo at +A_LOFF
// ---------------------------------------------------------------------------
__device__ __forceinline__ void warp_gemm(float acc[2][4][4], uint32_t ahBase,
                                          const uint32_t* __restrict__ bfrag,
                                          int mrow, int nw, int lane)
{
    int rowl   = lane & 15;
    int coloff = (lane >= 16) ? 16 : 0;

    uint32_t bh[2][4][2];
    #pragma unroll
    for (int nt = 0; nt < 4; nt++) {
        uint2 h = *(const uint2*)(bfrag + ((0 * 16 + (nw * 4 + nt)) * 32 + lane) * 2);
        bh[0][nt][0] = h.x; bh[0][nt][1] = h.y;
    }
    #pragma unroll
    for (int kt = 0; kt < 4; kt++) {
        int cur = kt & 1, nxt = cur ^ 1;
        if (kt < 3) {
            #pragma unroll
            for (int nt = 0; nt < 4; nt++) {
                uint2 h = *(const uint2*)(bfrag + (((kt + 1) * 16 + (nw * 4 + nt)) * 32 + lane) * 2);
                bh[nxt][nt][0] = h.x; bh[nxt][nt][1] = h.y;
            }
        }
        #pragma unroll
        for (int mt = 0; mt < 2; mt++) {
            uint32_t ah[4], al[4];
            uint32_t aoff = ahBase + (mrow + mt * 16 + rowl) * A_STRIDE + kt * 32 + coloff;
            ldmatrix4(ah, aoff);
            ldmatrix4(al, aoff + A_LOFF);
            #pragma unroll
            for (int nt = 0; nt < 4; nt++) mma16816(acc[mt][nt], ah, bh[cur][nt]);
            #pragma unroll
            for (int nt = 0; nt < 4; nt++) mma16816(acc[mt][nt], al, bh[cur][nt]);
        }
    }
}

// ---------------------------------------------------------------------------
// select device routine (256 threads, 8 warps): radix select + compaction
// ---------------------------------------------------------------------------
__device__ void do_select(char* smem, int b, int tid)
{
    unsigned* keys = (unsigned*)(smem + SM_KEYS);
    int*      hist = (int*)(smem + SM_HIST);     // [8][256]
    int*      total = (int*)(smem + SM_TOT);
    __shared__ unsigned s_prefix;
    __shared__ int s_rem, s_budget;
    __shared__ int wGt[8], wEq[8], preSel[8], preEq[8];

    int wid = tid >> 5, lane = tid & 31;

    for (int i = tid; i < Lc; i += 256) {
        unsigned u = __float_as_uint(g_scores[b * Lc + i]);
        keys[i] = u ^ (((unsigned)((int)u >> 31)) | 0x80000000u);
    }
    if (tid == 0) { s_prefix = 0u; s_rem = Kc; }
    __syncthreads();

    for (int shift = 24; shift >= 0; shift -= 8) {
        unsigned maskHigh = (shift == 24) ? 0u : (0xFFFFFFFFu << (shift + 8));
        #pragma unroll
        for (int j = 0; j < 8; j++) hist[j * 256 + tid] = 0;
        __syncthreads();
        unsigned prefix = s_prefix;
        #pragma unroll
        for (int c = 0; c < 16; c++) {
            unsigned k = keys[c * 256 + tid];
            if ((k & maskHigh) == prefix) {
                int bin = (k >> shift) & 255;
                unsigned mm  = __activemask();
                unsigned grp = __match_any_sync(mm, bin);
                if (lane == (__ffs(grp) - 1)) atomicAdd(&hist[wid * 256 + bin], __popc(grp));
            }
        }
        __syncthreads();
        {
            int c = 0;
            #pragma unroll
            for (int w = 0; w < 8; w++) c += hist[w * 256 + tid];
            total[tid] = c;
        }
        __syncthreads();
        if (wid == 0) {
            int base = lane * 8;
            int lsum = 0;
            #pragma unroll
            for (int j = 0; j < 8; j++) lsum += total[base + j];
            int v = lsum;
            #pragma unroll
            for (int off = 1; off < 32; off <<= 1) {
                int t = __shfl_down_sync(0xffffffffu, v, off);
                if (lane + off < 32) v += t;
            }
            int suf = v - lsum;
            int rem = s_rem;
            int running = suf;
            #pragma unroll
            for (int j = 7; j >= 0; j--) {
                int bin = base + j;
                int c = total[bin];
                if (running < rem && running + c >= rem) {
                    s_prefix = prefix | ((unsigned)bin << shift);
                    s_rem = rem - running;
                }
                running += c;
            }
        }
        __syncthreads();
    }
    unsigned T = s_prefix;

    int gtc = 0, eqc = 0;
    #pragma unroll
    for (int c = 0; c < 16; c++) {
        unsigned k = keys[wid * 512 + c * 32 + lane];
        gtc += (k > T); eqc += (k == T);
    }
    #pragma unroll
    for (int off = 16; off; off >>= 1) {
        gtc += __shfl_xor_sync(0xffffffffu, gtc, off);
        eqc += __shfl_xor_sync(0xffffffffu, eqc, off);
    }
    if (lane == 0) { wGt[wid] = gtc; wEq[wid] = eqc; }
    __syncthreads();
    if (tid == 0) {
        int totGt = 0;
        #pragma unroll
        for (int w = 0; w < 8; w++) totGt += wGt[w];
        int budget = Kc - totGt;
        int runSel = 0, runEq = 0;
        #pragma unroll
        for (int w = 0; w < 8; w++) {
            preSel[w] = runSel; preEq[w] = runEq;
            int eqSel = budget - runEq;
            if (eqSel < 0) eqSel = 0;
            if (eqSel > wEq[w]) eqSel = wEq[w];
            runSel += wGt[w] + eqSel;
            runEq  += wEq[w];
        }
        s_budget = budget;
    }
    __syncthreads();
    int budget = s_budget;
    int selOff = preSel[wid], eqOff = preEq[wid];
    unsigned below = (1u << lane) - 1u;
    #pragma unroll
    for (int c = 0; c < 16; c++) {
        int i = wid * 512 + c * 32 + lane;
        unsigned k = keys[i];
        bool isGt = (k > T), isEq = (k == T);
        unsigned balEq = __ballot_sync(0xffffffffu, isEq);
        int eqRank = eqOff + __popc(balEq & below);
        bool sel = isGt || (isEq && eqRank < budget);
        unsigned balSel = __ballot_sync(0xffffffffu, sel);
        int pos = selOff + __popc(balSel & below);
        if (sel) g_idx[b * Kc + pos] = i;
        selOff += __popc(balSel);
        eqOff  += __popc(balEq);
    }

    __threadfence();
    __syncthreads();
    if (tid == 0) atomicExch(&g_iflag[b], 1);
}

// ---------------------------------------------------------------------------
// 2. fused: [0,32) select | [32,288) sparse persistent | [288,736) full pers.
// ---------------------------------------------------------------------------
__global__ void __launch_bounds__(256, 3)
fused_mma(const float* __restrict__ x,  const float* __restrict__ spb,
          const float* __restrict__ fb, const float* __restrict__ lg,
          const float* __restrict__ lb, float* __restrict__ out)
{
    extern __shared__ char smem[];
    uint32_t sb = smem_u32(smem);
    int tid = threadIdx.x, warp = tid >> 5, lane = tid & 31;
    int nw = warp & 3, mg = warp >> 2, mrow = mg * 32;
    int cb = (lane & 3) * 2 + nw * 32;

    if (blockIdx.x < SEL_BLOCKS) {
        do_select(smem, blockIdx.x, tid);
        return;
    }

    if (blockIdx.x < SEL_BLOCKS + SP_BLOCKS) {
        // -------- sparse persistent: 4 gathered 64-row tiles, pipelined ----
        int bid = blockIdx.x - SEL_BLOCKS;
        int b = bid >> 3;                         // 8 blocks per batch
        const float* xb = x + (size_t)b * Lc * Cc;
        const int* idxb = &g_idx[b * Kc];
        float* spc = (float*)(smem + SM_SPC);
        float partAcc = 0.f;

        if (tid == 0) {
            while (atomicAdd(&g_iflag[b], 0) == 0) __nanosleep(100);
            __threadfence();
        }
        __syncthreads();

        int t0 = (bid & 7) * 4;
        convert_a(smem, SM_A0, xb, idxb + t0 * 64, 0, tid);
        int cur = 0;

        #pragma unroll
        for (int j = 0; j < 4; j++) {
            __syncthreads();                      // A(buf cur) ready; spc free

            float acc[2][4][4];
            #pragma unroll
            for (int i = 0; i < 2; i++)
                #pragma unroll
                for (int q = 0; q < 4; q++)
                    #pragma unroll
                    for (int k = 0; k < 4; k++) acc[i][q][k] = 0.f;

            warp_gemm(acc, sb + (cur ? SM_A1 : SM_A0), g_bfs, mrow, nw, lane);

            if (j < 3)
                convert_a(smem, cur ? SM_A0 : SM_A1, xb,
                          idxb + (t0 + j + 1) * 64, 0, tid);

            #pragma unroll
            for (int nt = 0; nt < 4; nt++) {
                int c = cb + nt * 8;
                float b0 = spb[c], b1 = spb[c + 1];
                float p0 = gelu_f(acc[0][nt][0] + b0) + gelu_f(acc[0][nt][2] + b0)
                         + gelu_f(acc[1][nt][0] + b0) + gelu_f(acc[1][nt][2] + b0);
                float p1 = gelu_f(acc[0][nt][1] + b1) + gelu_f(acc[0][nt][3] + b1)
                         + gelu_f(acc[1][nt][1] + b1) + gelu_f(acc[1][nt][3] + b1);
                #pragma unroll
                for (int off = 4; off <= 16; off <<= 1) {
                    p0 += __shfl_xor_sync(0xffffffffu, p0, off);
                    p1 += __shfl_xor_sync(0xffffffffu, p1, off);
                }
                if (lane < 4)
                    *(float2*)&spc[mg * 128 + c] = make_float2(p0, p1);
            }
            __syncthreads();
            if (tid < 128) partAcc += spc[tid] + spc[128 + tid];
            cur ^= 1;
        }
        if (tid < 128)
            g_part[(b * 8 + (bid & 7)) * Dc + tid] = partAcc;

        __shared__ int s_last;
        __threadfence();
        __syncthreads();
        if (tid == 0) s_last = (atomicAdd(&g_cnt[b], 1) == 7);
        __syncthreads();
        if (s_last) {
            if (tid < 128) {
                float s = 0.f;
                #pragma unroll
                for (int t = 0; t < 8; t++)
                    s += g_part[(b * 8 + t) * Dc + tid];
                g_agg[b * Dc + tid] = s * (1.0f / (float)Kc);
            }
            __threadfence();
            __syncthreads();
            if (tid == 0) atomicExch(&g_flag[b], 1);
        }
    } else {
        // -------- full persistent: grid-stride tiles, pipelined ------------
        int bid = blockIdx.x - SEL_BLOCKS - SP_BLOCKS;   // 0..447
        int tile = bid;
        int cur = 0;
        if (tile < FULL_TILES)
            convert_a(smem, SM_A0, x, nullptr, (long)tile * 64, tid);

        float2* red = (float2*)(smem + SM_RED);
        float2* mui = (float2*)(smem + SM_MUI);
        int r0 = lane >> 2;

        for (; tile < FULL_TILES; tile += FULL_PBLK) {
            __syncthreads();                 // A(buf cur) ready; red/mui free

            float acc[2][4][4];
            #pragma unroll
            for (int i = 0; i < 2; i++)
                #pragma unroll
                for (int q = 0; q < 4; q++)
                    #pragma unroll
                    for (int k = 0; k < 4; k++) acc[i][q][k] = 0.f;

            warp_gemm(acc, sb + (cur ? SM_A1 : SM_A0), g_bff, mrow, nw, lane);

            int nxtTile = tile + FULL_PBLK;
            if (nxtTile < FULL_TILES)
                convert_a(smem, cur ? SM_A0 : SM_A1, x, nullptr,
                          (long)nxtTile * 64, tid);

            int b = tile >> 6;
            long rowBase = (long)tile * 64;

            if (tid == 0) {
                while (atomicAdd(&g_flag[b], 0) == 0) __nanosleep(200);
                __threadfence();
            }
            __syncthreads();

            float gg[4][2], bb[4][2];
            #pragma unroll
            for (int nt = 0; nt < 4; nt++) {
                int c = cb + nt * 8;
                float b0 = fb[c]     + g_agg[b * Dc + c];
                float b1 = fb[c + 1] + g_agg[b * Dc + c + 1];
                gg[nt][0] = lg[c]; gg[nt][1] = lg[c + 1];
                bb[nt][0] = lb[c]; bb[nt][1] = lb[c + 1];
                #pragma unroll
                for (int mt = 0; mt < 2; mt++) {
                    acc[mt][nt][0] += b0; acc[mt][nt][1] += b1;
                    acc[mt][nt][2] += b0; acc[mt][nt][3] += b1;
                }
            }

            #pragma unroll
            for (int mt = 0; mt < 2; mt++) {
                #pragma unroll
                for (int h = 0; h < 2; h++) {
                    float S = 0.f, Q = 0.f;
                    #pragma unroll
                    for (int nt = 0; nt < 4; nt++) {
                        float v0 = acc[mt][nt][2 * h], v1 = acc[mt][nt][2 * h + 1];
                        S += v0 + v1; Q += v0 * v0 + v1 * v1;
                    }
                    S += __shfl_xor_sync(0xffffffffu, S, 1);
                    Q += __shfl_xor_sync(0xffffffffu, Q, 1);
                    S += __shfl_xor_sync(0xffffffffu, S, 2);
                    Q += __shfl_xor_sync(0xffffffffu, Q, 2);
                    if ((lane & 3) == 0)
                        red[(mrow + mt * 16 + r0 + 8 * h) * 4 + nw] = make_float2(S, Q);
                }
            }
            __syncthreads();
            if (tid < 64) {
                float2 a = red[tid * 4], c1 = red[tid * 4 + 1],
                       c2 = red[tid * 4 + 2], c3 = red[tid * 4 + 3];
                float Sr = a.x + c1.x + c2.x + c3.x;
                float Qr = a.y + c1.y + c2.y + c3.y;
                const float invD = 1.0f / 128.0f;
                float mu  = Sr * invD;
                float var = Qr * invD - mu * mu;
                mui[tid] = make_float2(mu, rsqrtf(var + 1e-5f));
            }
            __syncthreads();

            #pragma unroll
            for (int mt = 0; mt < 2; mt++) {
                #pragma unroll
                for (int h = 0; h < 2; h++) {
                    int row = mrow + mt * 16 + r0 + 8 * h;
                    float2 mi = mui[row];
                    float* op = out + (rowBase + row) * Dc;
                    #pragma unroll
                    for (int nt = 0; nt < 4; nt++) {
                        int c = cb + nt * 8;
                        float o0 = (acc[mt][nt][2*h]   - mi.x) * mi.y * gg[nt][0] + bb[nt][0];
                        float o1 = (acc[mt][nt][2*h+1] - mi.x) * mi.y * gg[nt][1] + bb[nt][1];
                        *(float2*)&op[c] = make_float2(o0, o1);
                    }
                }
            }
            cur ^= 1;
        }
    }
}

// ---------------------------------------------------------------------------
extern "C" void kernel_launch(void* const* d_in, const int* in_sizes, int n_in,
                              void* d_out, int out_size)
{
    const float* x   = (const float*)d_in[0];
    const float* sw  = (const float*)d_in[1];
    const float* sb  = (const float*)d_in[2];
    const float* spw = (const float*)d_in[3];
    const float* spb = (const float*)d_in[4];
    const float* fw  = (const float*)d_in[5];
    const float* fb  = (const float*)d_in[6];
    const float* lg  = (const float*)d_in[7];
    const float* lb  = (const float*)d_in[8];
    float* out = (float*)d_out;

    scores_kernel<<<(Bc * Lc) / 32, 256>>>(x, sw, sb, spw, fw);
    fused_mma<<<SEL_BLOCKS + SP_BLOCKS + FULL_PBLK, 256, SM_TOTAL>>>(
        x, spb, fb, lg, lb, out);
}

// round 16
// speedup vs baseline: 1.0362x; 1.0348x over previous
#include <cuda_runtime.h>
#include <cuda_fp16.h>
#include <math.h>
#include <stdint.h>

#define Bc 32
#define Lc 4096
#define Cc 64
#define Dc 128
#define Kc 2048
#define SP_TILES 16   // sparse tiles per batch: 2048/128

// ---------------- scratch (device globals; no allocs) -----------------------
__device__ float g_scores[Bc * Lc];
__device__ int   g_idx   [Bc * Kc];
__device__ float g_part  [Bc * SP_TILES * Dc];
__device__ float g_agg   [Bc * Dc];
__device__ int   g_cnt   [Bc];
// B fragments (fp16) in mma layout: [kt][nt][lane][reg] u32
__device__ __align__(16) uint32_t g_bff[4 * 16 * 32 * 2];  // full_w
__device__ __align__(16) uint32_t g_bfs[4 * 16 * 32 * 2];  // sparse_w

// ---------------- helpers ---------------------------------------------------
__device__ __forceinline__ uint32_t smem_u32(const void* p) {
    uint32_t a;
    asm("{ .reg .u64 t; cvta.to.shared.u64 t, %1; cvt.u32.u64 %0, t; }"
        : "=r"(a) : "l"(p));
    return a;
}
__device__ __forceinline__ uint32_t h2u(__half2 h) {
    return *reinterpret_cast<uint32_t*>(&h);
}
__device__ __forceinline__ void ldmatrix4(uint32_t* a, uint32_t addr) {
    asm volatile("ldmatrix.sync.aligned.m8n8.x4.shared.b16 {%0,%1,%2,%3}, [%4];"
                 : "=r"(a[0]), "=r"(a[1]), "=r"(a[2]), "=r"(a[3]) : "r"(addr));
}
__device__ __forceinline__ void mma16816(float* c, const uint32_t* a,
                                         const uint32_t* b) {
    asm volatile(
        "mma.sync.aligned.m16n8k16.row.col.f32.f16.f16.f32 "
        "{%0,%1,%2,%3}, {%4,%5,%6,%7}, {%8,%9}, {%0,%1,%2,%3};"
        : "+f"(c[0]), "+f"(c[1]), "+f"(c[2]), "+f"(c[3])
        : "r"(a[0]), "r"(a[1]), "r"(a[2]), "r"(a[3]), "r"(b[0]), "r"(b[1]));
}
__device__ __forceinline__ float gelu_f(float p) {
    float u = 1.5957691216f * p * (1.f + 0.044715f * p * p);
    u = fminf(u, 15.f);
    float e = __expf(u);
    return p * e / (e + 1.f);
}

// dynamic smem layout (bytes) — 128-row tiles (44KB < 48KB default limit)
#define SM_BASE  0        // 128 f32
#define SM_G     512
#define SM_B2    1024
#define SM_IDX   1536     // 128 ints
#define SM_SPC   2048     // 2*128 f32
#define SM_RED   3072     // 128*4 float2 = 4096
#define SM_MUI   7168     // 128 float2 = 1024
#define SM_AH    8192     // 128 rows * 144B = 18432
#define SM_AL    26624
#define SM_TOTAL 45056
#define A_STRIDE 144

// ---------------------------------------------------------------------------
// setup helper: fp16 B fragments in mma register layout (entry e in [0,4096))
// ---------------------------------------------------------------------------
__device__ __forceinline__ void setup_entry(int e, const float* __restrict__ spw,
                                            const float* __restrict__ fw)
{
    int reg  = e & 1;
    int lane = (e >> 1) & 31;
    int nt   = (e >> 6) & 15;
    int kt   = (e >> 10) & 3;
    int n = nt * 8 + (lane >> 2);
    int k = kt * 16 + reg * 8 + (lane & 3) * 2;
    g_bff[e] = h2u(__floats2half2_rn(fw[k * Dc + n],  fw[(k + 1) * Dc + n]));
    g_bfs[e] = h2u(__floats2half2_rn(spw[k * Dc + n], spw[(k + 1) * Dc + n]));
}

// ---------------------------------------------------------------------------
// 1. scores: 8 threads/row, float4 loads (+ setup & counter reset low blocks)
// ---------------------------------------------------------------------------
__global__ void scores_kernel(const float* __restrict__ x,
                              const float* __restrict__ sw,
                              const float* __restrict__ sb,
                              const float* __restrict__ spw,
                              const float* __restrict__ fw)
{
    int tid = threadIdx.x;
    if (blockIdx.x < 4) {
        int e0 = blockIdx.x * 1024 + tid;
        #pragma unroll
        for (int j = 0; j < 4; j++) setup_entry(e0 + j * 256, spw, fw);
    }
    if (blockIdx.x == 4 && tid < Bc) g_cnt[tid] = 0;

    int row = blockIdx.x * 32 + (tid >> 3);   // grid = B*L/32 = 4096
    int j   = tid & 7;
    const float4* xr = (const float4*)(x + (size_t)row * Cc + j * 8);
    float4 a = xr[0], c = xr[1];
    const float4* wp = (const float4*)(sw + j * 8);
    float4 w0 = wp[0], w1 = wp[1];
    float s = a.x*w0.x + a.y*w0.y + a.z*w0.z + a.w*w0.w
            + c.x*w1.x + c.y*w1.y + c.z*w1.z + c.w*w1.w;
    s += __shfl_xor_sync(0xffffffffu, s, 1);
    s += __shfl_xor_sync(0xffffffffu, s, 2);
    s += __shfl_xor_sync(0xffffffffu, s, 4);
    if (j == 0) g_scores[row] = s + sb[0];
}

// ---------------------------------------------------------------------------
// 2. 8-bit radix select (4 passes) + segment-per-warp ordered compaction
// ---------------------------------------------------------------------------
__global__ void __launch_bounds__(512)
select_kernel()
{
    __shared__ unsigned keys[Lc];         // 16 KB
    __shared__ int      hist[16][256];    // 16 KB
    __shared__ int      total[256];
    __shared__ unsigned s_prefix;
    __shared__ int      s_rem;
    __shared__ int      wGt[16], wEq[16], preSel[16], preEq[16];
    __shared__ int      s_budget;

    int tid  = threadIdx.x;               // 512
    int wid  = tid >> 5;
    int lane = tid & 31;
    int b    = blockIdx.x;

    for (int i = tid; i < Lc; i += 512) {
        unsigned u = __float_as_uint(g_scores[b * Lc + i]);
        keys[i] = u ^ (((unsigned)((int)u >> 31)) | 0x80000000u);
    }
    if (tid == 0) { s_prefix = 0u; s_rem = Kc; }
    __syncthreads();

    for (int shift = 24; shift >= 0; shift -= 8) {
        unsigned maskHigh = (shift == 24) ? 0u : (0xFFFFFFFFu << (shift + 8));
        #pragma unroll
        for (int j = 0; j < 8; j++) hist[(tid >> 8) * 8 + j][tid & 255] = 0;
        __syncthreads();
        unsigned prefix = s_prefix;
        #pragma unroll
        for (int c = 0; c < 8; c++) {
            int i = c * 512 + tid;
            unsigned k = keys[i];
            if ((k & maskHigh) == prefix) {
                int bin = (k >> shift) & 255;
                unsigned mm  = __activemask();
                unsigned grp = __match_any_sync(mm, bin);
                if (lane == (__ffs(grp) - 1)) atomicAdd(&hist[wid][bin], __popc(grp));
            }
        }
        __syncthreads();
        if (tid < 256) {
            int c = 0;
            #pragma unroll
            for (int w = 0; w < 16; w++) c += hist[w][tid];
            total[tid] = c;
        }
        __syncthreads();
        if (wid == 0) {
            int base = lane * 8;
            int lsum = 0;
            #pragma unroll
            for (int j = 0; j < 8; j++) lsum += total[base + j];
            int v = lsum;
            #pragma unroll
            for (int off = 1; off < 32; off <<= 1) {
                int t = __shfl_down_sync(0xffffffffu, v, off);
                if (lane + off < 32) v += t;
            }
            int suf = v - lsum;
            int rem = s_rem;
            int running = suf;
            #pragma unroll
            for (int j = 7; j >= 0; j--) {
                int bin = base + j;
                int c = total[bin];
                if (running < rem && running + c >= rem) {
                    s_prefix = prefix | ((unsigned)bin << shift);
                    s_rem = rem - running;
                }
                running += c;
            }
        }
        __syncthreads();
    }
    unsigned T = s_prefix;

    int gtc = 0, eqc = 0;
    #pragma unroll
    for (int c = 0; c < 8; c++) {
        unsigned k = keys[wid * 256 + c * 32 + lane];
        gtc += (k > T); eqc += (k == T);
    }
    #pragma unroll
    for (int off = 16; off; off >>= 1) {
        gtc += __shfl_xor_sync(0xffffffffu, gtc, off);
        eqc += __shfl_xor_sync(0xffffffffu, eqc, off);
    }
    if (lane == 0) { wGt[wid] = gtc; wEq[wid] = eqc; }
    __syncthreads();
    if (tid == 0) {
        int totGt = 0;
        #pragma unroll
        for (int w = 0; w < 16; w++) totGt += wGt[w];
        int budget = Kc - totGt;
        int runSel = 0, runEq = 0;
        #pragma unroll
        for (int w = 0; w < 16; w++) {
            preSel[w] = runSel; preEq[w] = runEq;
            int eqSel = budget - runEq;
            if (eqSel < 0) eqSel = 0;
            if (eqSel > wEq[w]) eqSel = wEq[w];
            runSel += wGt[w] + eqSel;
            runEq  += wEq[w];
        }
        s_budget = budget;
    }
    __syncthreads();
    int budget = s_budget;
    int selOff = preSel[wid], eqOff = preEq[wid];
    unsigned below = (1u << lane) - 1u;
    #pragma unroll
    for (int c = 0; c < 8; c++) {
        int i = wid * 256 + c * 32 + lane;
        unsigned k = keys[i];
        bool isGt = (k > T), isEq = (k == T);
        unsigned balEq = __ballot_sync(0xffffffffu, isEq);
        int eqRank = eqOff + __popc(balEq & below);
        bool sel = isGt || (isEq && eqRank < budget);
        unsigned balSel = __ballot_sync(0xffffffffu, sel);
        int pos = selOff + __popc(balSel & below);
        if (sel) g_idx[b * Kc + pos] = i;
        selOff += __popc(balSel);
        eqOff  += __popc(balEq);
    }
}

// ---------------------------------------------------------------------------
// convert 128 x-rows (f32) -> split fp16 A tiles in smem. 256 threads.
// ---------------------------------------------------------------------------
__device__ __forceinline__ void convert_a(char* smem, const float* __restrict__ xbase,
                                          const int* rowSrc, long rowBase, int tid)
{
    #pragma unroll
    for (int it = 0; it < 8; it++) {
        int idx4 = it * 256 + tid;          // 2048 float4 = 128 rows x 16
        int row  = idx4 >> 4;
        int k4   = idx4 & 15;
        long gr  = rowSrc ? (long)rowSrc[row] : (rowBase + row);
        float4 v = *(const float4*)(xbase + gr * Cc + k4 * 4);
        __half2 h01 = __floats2half2_rn(v.x, v.y);
        __half2 h23 = __floats2half2_rn(v.z, v.w);
        __half2 l01 = __floats2half2_rn(v.x - __low2float(h01),
                                        v.y - __high2float(h01));
        __half2 l23 = __floats2half2_rn(v.z - __low2float(h23),
                                        v.w - __high2float(h23));
        int off = row * A_STRIDE + k4 * 8;
        *(uint2*)(smem + SM_AH + off) = make_uint2(h2u(h01), h2u(h23));
        *(uint2*)(smem + SM_AL + off) = make_uint2(h2u(l01), h2u(l23));
    }
}

// ---------------------------------------------------------------------------
// warp GEMM (fp16 2-term): rows [mrow,mrow+64) x cols [nw*32,nw*32+32)
// ---------------------------------------------------------------------------
__device__ __forceinline__ void warp_gemm(float acc[4][4][4], uint32_t sbase,
                                          const uint32_t* __restrict__ bfrag,
                                          int mrow, int nw, int lane)
{
    int rowl   = lane & 15;
    int coloff = (lane >= 16) ? 16 : 0;

    uint32_t bh[2][4][2];
    #pragma unroll
    for (int nt = 0; nt < 4; nt++) {
        uint2 h = *(const uint2*)(bfrag + ((0 * 16 + (nw * 4 + nt)) * 32 + lane) * 2);
        bh[0][nt][0] = h.x; bh[0][nt][1] = h.y;
    }
    #pragma unroll
    for (int kt = 0; kt < 4; kt++) {
        int cur = kt & 1, nxt = cur ^ 1;
        if (kt < 3) {
            #pragma unroll
            for (int nt = 0; nt < 4; nt++) {
                uint2 h = *(const uint2*)(bfrag + (((kt + 1) * 16 + (nw * 4 + nt)) * 32 + lane) * 2);
                bh[nxt][nt][0] = h.x; bh[nxt][nt][1] = h.y;
            }
        }
        #pragma unroll
        for (int mt = 0; mt < 4; mt++) {
            uint32_t ah[4], al[4];
            uint32_t aoff = (mrow + mt * 16 + rowl) * A_STRIDE + kt * 32 + coloff;
            ldmatrix4(ah, sbase + SM_AH + aoff);
            ldmatrix4(al, sbase + SM_AL + aoff);
            #pragma unroll
            for (int nt = 0; nt < 4; nt++) mma16816(acc[mt][nt], ah, bh[cur][nt]);
            #pragma unroll
            for (int nt = 0; nt < 4; nt++) mma16816(acc[mt][nt], al, bh[cur][nt]);
        }
    }
}

// ---------------------------------------------------------------------------
// 3. sparse: gathered 128-row tile GEMM + gelu + column sums + fused agg
// ---------------------------------------------------------------------------
__global__ void __launch_bounds__(256, 2)
sparse_mma(const float* __restrict__ x, const float* __restrict__ spb)
{
    extern __shared__ char smem[];
    uint32_t sb = smem_u32(smem);
    int tid = threadIdx.x, warp = tid >> 5, lane = tid & 31;
    int nw = warp & 3, mg = warp >> 2, mrow = mg * 64;
    int blk = blockIdx.x;                 // Bc*16 = 512
    int b = blk >> 4, tile = blk & 15;

    if (tid < 128) {
        ((int*)(smem + SM_IDX))[tid] = g_idx[b * Kc + tile * 128 + tid];
        *(float*)(smem + SM_BASE + tid * 4) = spb[tid];
    }
    __syncthreads();

    convert_a(smem, x + (size_t)b * Lc * Cc, (const int*)(smem + SM_IDX), 0, tid);
    __syncthreads();

    float acc[4][4][4];
    #pragma unroll
    for (int i = 0; i < 4; i++)
        #pragma unroll
        for (int j = 0; j < 4; j++)
            #pragma unroll
            for (int k = 0; k < 4; k++) acc[i][j][k] = 0.f;

    warp_gemm(acc, sb, g_bfs, mrow, nw, lane);

    // fragment gelu + column partial sums (per warp over its 64 rows)
    const float* bs = (const float*)(smem + SM_BASE);
    float* spc = (float*)(smem + SM_SPC);
    int cb = (lane & 3) * 2 + nw * 32;
    #pragma unroll
    for (int nt = 0; nt < 4; nt++) {
        float b0 = bs[cb + nt * 8], b1 = bs[cb + nt * 8 + 1];
        float p0 = 0.f, p1 = 0.f;
        #pragma unroll
        for (int mt = 0; mt < 4; mt++) {
            p0 += gelu_f(acc[mt][nt][0] + b0) + gelu_f(acc[mt][nt][2] + b0);
            p1 += gelu_f(acc[mt][nt][1] + b1) + gelu_f(acc[mt][nt][3] + b1);
        }
        #pragma unroll
        for (int off = 4; off <= 16; off <<= 1) {
            p0 += __shfl_xor_sync(0xffffffffu, p0, off);
            p1 += __shfl_xor_sync(0xffffffffu, p1, off);
        }
        if (lane < 4)
            *(float2*)&spc[mg * 128 + cb + nt * 8] = make_float2(p0, p1);
    }
    __syncthreads();
    if (tid < 128)
        g_part[blk * Dc + tid] = spc[tid] + spc[128 + tid];

    // last block of this batch reduces partials -> mean (threadfence pattern)
    __shared__ int s_last;
    __threadfence();
    __syncthreads();
    if (tid == 0) s_last = (atomicAdd(&g_cnt[b], 1) == SP_TILES - 1);
    __syncthreads();
    if (s_last && tid < 128) {
        float s = 0.f;
        #pragma unroll
        for (int t = 0; t < SP_TILES; t++) s += g_part[(b * SP_TILES + t) * Dc + tid];
        g_agg[b * Dc + tid] = s * (1.0f / (float)Kc);
    }
}

// ---------------------------------------------------------------------------
// 4. full: 128-row tile GEMM + base + fragment LayerNorm + direct STG
// ---------------------------------------------------------------------------
__global__ void __launch_bounds__(256, 2)
full_mma(const float* __restrict__ x,  const float* __restrict__ fb,
         const float* __restrict__ lg, const float* __restrict__ lb,
         float* __restrict__ out)
{
    extern __shared__ char smem[];
    uint32_t sb = smem_u32(smem);
    int tid = threadIdx.x, warp = tid >> 5, lane = tid & 31;
    int nw = warp & 3, mg = warp >> 2, mrow = mg * 64;
    long rowBase = (long)blockIdx.x * 128;   // grid = 1024
    int b = blockIdx.x >> 5;                 // 32 tiles per batch

    if (tid < 128) {
        *(float*)(smem + SM_BASE + tid * 4) = fb[tid] + g_agg[b * Dc + tid];
        *(float*)(smem + SM_G  + tid * 4) = lg[tid];
        *(float*)(smem + SM_B2 + tid * 4) = lb[tid];
    }

    convert_a(smem, x, nullptr, rowBase, tid);
    __syncthreads();

    float acc[4][4][4];
    #pragma unroll
    for (int i = 0; i < 4; i++)
        #pragma unroll
        for (int j = 0; j < 4; j++)
            #pragma unroll
            for (int k = 0; k < 4; k++) acc[i][j][k] = 0.f;

    warp_gemm(acc, sb, g_bff, mrow, nw, lane);

    const float* bs = (const float*)(smem + SM_BASE);
    const float* gs = (const float*)(smem + SM_G);
    const float* ts = (const float*)(smem + SM_B2);
    int cb = (lane & 3) * 2 + nw * 32;
    float gg[4][2], bb[4][2];
    #pragma unroll
    for (int nt = 0; nt < 4; nt++) {
        int c = cb + nt * 8;
        float b0 = bs[c], b1 = bs[c + 1];
        gg[nt][0] = gs[c]; gg[nt][1] = gs[c + 1];
        bb[nt][0] = ts[c]; bb[nt][1] = ts[c + 1];
        #pragma unroll
        for (int mt = 0; mt < 4; mt++) {
            acc[mt][nt][0] += b0; acc[mt][nt][1] += b1;
            acc[mt][nt][2] += b0; acc[mt][nt][3] += b1;
        }
    }

    // row stats: quad butterfly then cross-warp combine via smem
    float2* red = (float2*)(smem + SM_RED);
    int r0 = lane >> 2;
    #pragma unroll
    for (int mt = 0; mt < 4; mt++) {
        #pragma unroll
        for (int h = 0; h < 2; h++) {
            float S = 0.f, Q = 0.f;
            #pragma unroll
            for (int nt = 0; nt < 4; nt++) {
                float v0 = acc[mt][nt][2 * h], v1 = acc[mt][nt][2 * h + 1];
                S += v0 + v1; Q += v0 * v0 + v1 * v1;
            }
            S += __shfl_xor_sync(0xffffffffu, S, 1);
            Q += __shfl_xor_sync(0xffffffffu, Q, 1);
            S += __shfl_xor_sync(0xffffffffu, S, 2);
            Q += __shfl_xor_sync(0xffffffffu, Q, 2);
            if ((lane & 3) == 0)
                red[(mrow + mt * 16 + r0 + 8 * h) * 4 + nw] = make_float2(S, Q);
        }
    }
    __syncthreads();
    float2* mui = (float2*)(smem + SM_MUI);
    if (tid < 128) {
        float2 a = red[tid * 4], c1 = red[tid * 4 + 1],
               c2 = red[tid * 4 + 2], c3 = red[tid * 4 + 3];
        float Sr = a.x + c1.x + c2.x + c3.x;
        float Qr = a.y + c1.y + c2.y + c3.y;
        const float invD = 1.0f / 128.0f;
        float mu  = Sr * invD;
        float var = Qr * invD - mu * mu;
        mui[tid] = make_float2(mu, rsqrtf(var + 1e-5f));
    }
    __syncthreads();

    #pragma unroll
    for (int mt = 0; mt < 4; mt++) {
        #pragma unroll
        for (int h = 0; h < 2; h++) {
            int row = mrow + mt * 16 + r0 + 8 * h;
            float2 mi = mui[row];
            float* op = out + (rowBase + row) * Dc;
            #pragma unroll
            for (int nt = 0; nt < 4; nt++) {
                int c = cb + nt * 8;
                float o0 = (acc[mt][nt][2*h]   - mi.x) * mi.y * gg[nt][0] + bb[nt][0];
                float o1 = (acc[mt][nt][2*h+1] - mi.x) * mi.y * gg[nt][1] + bb[nt][1];
                *(float2*)&op[c] = make_float2(o0, o1);
            }
        }
    }
}

// ---------------------------------------------------------------------------
extern "C" void kernel_launch(void* const* d_in, const int* in_sizes, int n_in,
                              void* d_out, int out_size)
{
    const float* x   = (const float*)d_in[0];
    const float* sw  = (const float*)d_in[1];
    const float* sb  = (const float*)d_in[2];
    const float* spw = (const float*)d_in[3];
    const float* spb = (const float*)d_in[4];
    const float* fw  = (const float*)d_in[5];
    const float* fb  = (const float*)d_in[6];
    const float* lg  = (const float*)d_in[7];
    const float* lb  = (const float*)d_in[8];
    float* out = (float*)d_out;

    scores_kernel<<<(Bc * Lc) / 32, 256>>>(x, sw, sb, spw, fw);
    select_kernel<<<Bc, 512>>>();
    sparse_mma<<<Bc * SP_TILES, 256, SM_TOTAL>>>(x, spb);
    full_mma<<<(Bc * Lc) / 128, 256, SM_TOTAL>>>(x, fb, lg, lb, out);
}

// round 17
// speedup vs baseline: 1.1646x; 1.1240x over previous
#include <cuda_runtime.h>
#include <cuda_fp16.h>
#include <math.h>
#include <stdint.h>

#define Bc 32
#define Lc 4096
#define Cc 64
#define Dc 128
#define Kc 2048
#define SP_TILES 16   // sparse tiles per batch: 2048/128

// ---------------- scratch (device globals; no allocs) -----------------------
__device__ float g_scores[Bc * Lc];
__device__ int   g_idx   [Bc * Kc];
__device__ float g_part  [Bc * SP_TILES * Dc];
__device__ float g_agg   [Bc * Dc];
__device__ int   g_cnt   [Bc];
// B fragments (fp16) in mma layout: [kt][nt][lane][reg] u32
__device__ __align__(16) uint32_t g_bff[4 * 16 * 32 * 2];  // full_w
__device__ __align__(16) uint32_t g_bfs[4 * 16 * 32 * 2];  // sparse_w

// ---------------- helpers ---------------------------------------------------
__device__ __forceinline__ uint32_t smem_u32(const void* p) {
    uint32_t a;
    asm("{ .reg .u64 t; cvta.to.shared.u64 t, %1; cvt.u32.u64 %0, t; }"
        : "=r"(a) : "l"(p));
    return a;
}
__device__ __forceinline__ uint32_t h2u(__half2 h) {
    return *reinterpret_cast<uint32_t*>(&h);
}
__device__ __forceinline__ void ldmatrix4(uint32_t* a, uint32_t addr) {
    asm volatile("ldmatrix.sync.aligned.m8n8.x4.shared.b16 {%0,%1,%2,%3}, [%4];"
                 : "=r"(a[0]), "=r"(a[1]), "=r"(a[2]), "=r"(a[3]) : "r"(addr));
}
__device__ __forceinline__ void mma16816(float* c, const uint32_t* a,
                                         const uint32_t* b) {
    asm volatile(
        "mma.sync.aligned.m16n8k16.row.col.f32.f16.f16.f32 "
        "{%0,%1,%2,%3}, {%4,%5,%6,%7}, {%8,%9}, {%0,%1,%2,%3};"
        : "+f"(c[0]), "+f"(c[1]), "+f"(c[2]), "+f"(c[3])
        : "r"(a[0]), "r"(a[1]), "r"(a[2]), "r"(a[3]), "r"(b[0]), "r"(b[1]));
}
__device__ __forceinline__ float gelu_f(float p) {
    float u = 1.5957691216f * p * (1.f + 0.044715f * p * p);
    u = fminf(u, 15.f);
    float e = __expf(u);
    return p * e / (e + 1.f);
}

// dynamic smem layout (bytes) — 128-row tiles, single fp16 A plane
#define SM_BASE  0        // 128 f32
#define SM_G     512
#define SM_B2    1024
#define SM_IDX   1536     // 128 ints
#define SM_SPC   2048     // 2*128 f32
#define SM_RED   3072     // 128*4 float2 = 4096
#define SM_MUI   7168     // 128 float2 = 1024
#define SM_AH    8192     // 128 rows * 144B = 18432
#define SM_TOTAL 26624
#define A_STRIDE 144

// ---------------------------------------------------------------------------
// setup helper: fp16 B fragments in mma register layout (entry e in [0,4096))
// ---------------------------------------------------------------------------
__device__ __forceinline__ void setup_entry(int e, const float* __restrict__ spw,
                                            const float* __restrict__ fw)
{
    int reg  = e & 1;
    int lane = (e >> 1) & 31;
    int nt   = (e >> 6) & 15;
    int kt   = (e >> 10) & 3;
    int n = nt * 8 + (lane >> 2);
    int k = kt * 16 + reg * 8 + (lane & 3) * 2;
    g_bff[e] = h2u(__floats2half2_rn(fw[k * Dc + n],  fw[(k + 1) * Dc + n]));
    g_bfs[e] = h2u(__floats2half2_rn(spw[k * Dc + n], spw[(k + 1) * Dc + n]));
}

// ---------------------------------------------------------------------------
// 1. scores: 8 threads/row, float4 loads (+ setup & counter reset low blocks)
// ---------------------------------------------------------------------------
__global__ void scores_kernel(const float* __restrict__ x,
                              const float* __restrict__ sw,
                              const float* __restrict__ sb,
                              const float* __restrict__ spw,
                              const float* __restrict__ fw)
{
    int tid = threadIdx.x;
    if (blockIdx.x < 4) {
        int e0 = blockIdx.x * 1024 + tid;
        #pragma unroll
        for (int j = 0; j < 4; j++) setup_entry(e0 + j * 256, spw, fw);
    }
    if (blockIdx.x == 4 && tid < Bc) g_cnt[tid] = 0;

    int row = blockIdx.x * 32 + (tid >> 3);   // grid = B*L/32 = 4096
    int j   = tid & 7;
    const float4* xr = (const float4*)(x + (size_t)row * Cc + j * 8);
    float4 a = xr[0], c = xr[1];
    const float4* wp = (const float4*)(sw + j * 8);
    float4 w0 = wp[0], w1 = wp[1];
    float s = a.x*w0.x + a.y*w0.y + a.z*w0.z + a.w*w0.w
            + c.x*w1.x + c.y*w1.y + c.z*w1.z + c.w*w1.w;
    s += __shfl_xor_sync(0xffffffffu, s, 1);
    s += __shfl_xor_sync(0xffffffffu, s, 2);
    s += __shfl_xor_sync(0xffffffffu, s, 4);
    if (j == 0) g_scores[row] = s + sb[0];
}

// ---------------------------------------------------------------------------
// 2. 8-bit radix select (4 passes) + segment-per-warp ordered compaction
// ---------------------------------------------------------------------------
__global__ void __launch_bounds__(512)
select_kernel()
{
    __shared__ unsigned keys[Lc];         // 16 KB
    __shared__ int      hist[16][256];    // 16 KB
    __shared__ int      total[256];
    __shared__ unsigned s_prefix;
    __shared__ int      s_rem;
    __shared__ int      wGt[16], wEq[16], preSel[16], preEq[16];
    __shared__ int      s_budget;

    int tid  = threadIdx.x;               // 512
    int wid  = tid >> 5;
    int lane = tid & 31;
    int b    = blockIdx.x;

    for (int i = tid; i < Lc; i += 512) {
        unsigned u = __float_as_uint(g_scores[b * Lc + i]);
        keys[i] = u ^ (((unsigned)((int)u >> 31)) | 0x80000000u);
    }
    if (tid == 0) { s_prefix = 0u; s_rem = Kc; }
    __syncthreads();

    for (int shift = 24; shift >= 0; shift -= 8) {
        unsigned maskHigh = (shift == 24) ? 0u : (0xFFFFFFFFu << (shift + 8));
        #pragma unroll
        for (int j = 0; j < 8; j++) hist[(tid >> 8) * 8 + j][tid & 255] = 0;
        __syncthreads();
        unsigned prefix = s_prefix;
        #pragma unroll
        for (int c = 0; c < 8; c++) {
            int i = c * 512 + tid;
            unsigned k = keys[i];
            if ((k & maskHigh) == prefix) {
                int bin = (k >> shift) & 255;
                unsigned mm  = __activemask();
                unsigned grp = __match_any_sync(mm, bin);
                if (lane == (__ffs(grp) - 1)) atomicAdd(&hist[wid][bin], __popc(grp));
            }
        }
        __syncthreads();
        if (tid < 256) {
            int c = 0;
            #pragma unroll
            for (int w = 0; w < 16; w++) c += hist[w][tid];
            total[tid] = c;
        }
        __syncthreads();
        if (wid == 0) {
            int base = lane * 8;
            int lsum = 0;
            #pragma unroll
            for (int j = 0; j < 8; j++) lsum += total[base + j];
            int v = lsum;
            #pragma unroll
            for (int off = 1; off < 32; off <<= 1) {
                int t = __shfl_down_sync(0xffffffffu, v, off);
                if (lane + off < 32) v += t;
            }
            int suf = v - lsum;
            int rem = s_rem;
            int running = suf;
            #pragma unroll
            for (int j = 7; j >= 0; j--) {
                int bin = base + j;
                int c = total[bin];
                if (running < rem && running + c >= rem) {
                    s_prefix = prefix | ((unsigned)bin << shift);
                    s_rem = rem - running;
                }
                running += c;
            }
        }
        __syncthreads();
    }
    unsigned T = s_prefix;

    int gtc = 0, eqc = 0;
    #pragma unroll
    for (int c = 0; c < 8; c++) {
        unsigned k = keys[wid * 256 + c * 32 + lane];
        gtc += (k > T); eqc += (k == T);
    }
    #pragma unroll
    for (int off = 16; off; off >>= 1) {
        gtc += __shfl_xor_sync(0xffffffffu, gtc, off);
        eqc += __shfl_xor_sync(0xffffffffu, eqc, off);
    }
    if (lane == 0) { wGt[wid] = gtc; wEq[wid] = eqc; }
    __syncthreads();
    if (tid == 0) {
        int totGt = 0;
        #pragma unroll
        for (int w = 0; w < 16; w++) totGt += wGt[w];
        int budget = Kc - totGt;
        int runSel = 0, runEq = 0;
        #pragma unroll
        for (int w = 0; w < 16; w++) {
            preSel[w] = runSel; preEq[w] = runEq;
            int eqSel = budget - runEq;
            if (eqSel < 0) eqSel = 0;
            if (eqSel > wEq[w]) eqSel = wEq[w];
            runSel += wGt[w] + eqSel;
            runEq  += wEq[w];
        }
        s_budget = budget;
    }
    __syncthreads();
    int budget = s_budget;
    int selOff = preSel[wid], eqOff = preEq[wid];
    unsigned below = (1u << lane) - 1u;
    #pragma unroll
    for (int c = 0; c < 8; c++) {
        int i = wid * 256 + c * 32 + lane;
        unsigned k = keys[i];
        bool isGt = (k > T), isEq = (k == T);
        unsigned balEq = __ballot_sync(0xffffffffu, isEq);
        int eqRank = eqOff + __popc(balEq & below);
        bool sel = isGt || (isEq && eqRank < budget);
        unsigned balSel = __ballot_sync(0xffffffffu, sel);
        int pos = selOff + __popc(balSel & below);
        if (sel) g_idx[b * Kc + pos] = i;
        selOff += __popc(balSel);
        eqOff  += __popc(balEq);
    }
}

// ---------------------------------------------------------------------------
// convert 128 x-rows (f32) -> fp16 A tile in smem. 256 threads.
// ---------------------------------------------------------------------------
__device__ __forceinline__ void convert_a(char* smem, const float* __restrict__ xbase,
                                          const int* rowSrc, long rowBase, int tid)
{
    #pragma unroll
    for (int it = 0; it < 8; it++) {
        int idx4 = it * 256 + tid;          // 2048 float4 = 128 rows x 16
        int row  = idx4 >> 4;
        int k4   = idx4 & 15;
        long gr  = rowSrc ? (long)rowSrc[row] : (rowBase + row);
        float4 v = *(const float4*)(xbase + gr * Cc + k4 * 4);
        __half2 h01 = __floats2half2_rn(v.x, v.y);
        __half2 h23 = __floats2half2_rn(v.z, v.w);
        int off = row * A_STRIDE + k4 * 8;
        *(uint2*)(smem + SM_AH + off) = make_uint2(h2u(h01), h2u(h23));
    }
}

// ---------------------------------------------------------------------------
// warp GEMM (fp16 single-term): rows [mrow,mrow+64) x cols [nw*32,nw*32+32)
// ---------------------------------------------------------------------------
__device__ __forceinline__ void warp_gemm(float acc[4][4][4], uint32_t sbase,
                                          const uint32_t* __restrict__ bfrag,
                                          int mrow, int nw, int lane)
{
    int rowl   = lane & 15;
    int coloff = (lane >= 16) ? 16 : 0;

    uint32_t bh[2][4][2];
    #pragma unroll
    for (int nt = 0; nt < 4; nt++) {
        uint2 h = *(const uint2*)(bfrag + ((0 * 16 + (nw * 4 + nt)) * 32 + lane) * 2);
        bh[0][nt][0] = h.x; bh[0][nt][1] = h.y;
    }
    #pragma unroll
    for (int kt = 0; kt < 4; kt++) {
        int cur = kt & 1, nxt = cur ^ 1;
        if (kt < 3) {
            #pragma unroll
            for (int nt = 0; nt < 4; nt++) {
                uint2 h = *(const uint2*)(bfrag + (((kt + 1) * 16 + (nw * 4 + nt)) * 32 + lane) * 2);
                bh[nxt][nt][0] = h.x; bh[nxt][nt][1] = h.y;
            }
        }
        #pragma unroll
        for (int mt = 0; mt < 4; mt++) {
            uint32_t ah[4];
            uint32_t aoff = (mrow + mt * 16 + rowl) * A_STRIDE + kt * 32 + coloff;
            ldmatrix4(ah, sbase + SM_AH + aoff);
            #pragma unroll
            for (int nt = 0; nt < 4; nt++) mma16816(acc[mt][nt], ah, bh[cur][nt]);
        }
    }
}

// ---------------------------------------------------------------------------
// 3. sparse: gathered 128-row tile GEMM + gelu + column sums + fused agg
// ---------------------------------------------------------------------------
__global__ void __launch_bounds__(256, 2)
sparse_mma(const float* __restrict__ x, const float* __restrict__ spb)
{
    extern __shared__ char smem[];
    uint32_t sb = smem_u32(smem);
    int tid = threadIdx.x, warp = tid >> 5, lane = tid & 31;
    int nw = warp & 3, mg = warp >> 2, mrow = mg * 64;
    int blk = blockIdx.x;                 // Bc*16 = 512
    int b = blk >> 4, tile = blk & 15;

    if (tid < 128) {
        ((int*)(smem + SM_IDX))[tid] = g_idx[b * Kc + tile * 128 + tid];
        *(float*)(smem + SM_BASE + tid * 4) = spb[tid];
    }
    __syncthreads();

    convert_a(smem, x + (size_t)b * Lc * Cc, (const int*)(smem + SM_IDX), 0, tid);
    __syncthreads();

    float acc[4][4][4];
    #pragma unroll
    for (int i = 0; i < 4; i++)
        #pragma unroll
        for (int j = 0; j < 4; j++)
            #pragma unroll
            for (int k = 0; k < 4; k++) acc[i][j][k] = 0.f;

    warp_gemm(acc, sb, g_bfs, mrow, nw, lane);

    // fragment gelu + column partial sums (per warp over its 64 rows)
    const float* bs = (const float*)(smem + SM_BASE);
    float* spc = (float*)(smem + SM_SPC);
    int cb = (lane & 3) * 2 + nw * 32;
    #pragma unroll
    for (int nt = 0; nt < 4; nt++) {
        float b0 = bs[cb + nt * 8], b1 = bs[cb + nt * 8 + 1];
        float p0 = 0.f, p1 = 0.f;
        #pragma unroll
        for (int mt = 0; mt < 4; mt++) {
            p0 += gelu_f(acc[mt][nt][0] + b0) + gelu_f(acc[mt][nt][2] + b0);
            p1 += gelu_f(acc[mt][nt][1] + b1) + gelu_f(acc[mt][nt][3] + b1);
        }
        #pragma unroll
        for (int off = 4; off <= 16; off <<= 1) {
            p0 += __shfl_xor_sync(0xffffffffu, p0, off);
            p1 += __shfl_xor_sync(0xffffffffu, p1, off);
        }
        if (lane < 4)
            *(float2*)&spc[mg * 128 + cb + nt * 8] = make_float2(p0, p1);
    }
    __syncthreads();
    if (tid < 128)
        g_part[blk * Dc + tid] = spc[tid] + spc[128 + tid];

    // last block of this batch reduces partials -> mean (threadfence pattern)
    __shared__ int s_last;
    __threadfence();
    __syncthreads();
    if (tid == 0) s_last = (atomicAdd(&g_cnt[b], 1) == SP_TILES - 1);
    __syncthreads();
    if (s_last && tid < 128) {
        float s = 0.f;
        #pragma unroll
        for (int t = 0; t < SP_TILES; t++) s += g_part[(b * SP_TILES + t) * Dc + tid];
        g_agg[b * Dc + tid] = s * (1.0f / (float)Kc);
    }
}

// ---------------------------------------------------------------------------
// 4. full: 128-row tile GEMM + base + fragment LayerNorm + direct STG
// ---------------------------------------------------------------------------
__global__ void __launch_bounds__(256, 2)
full_mma(const float* __restrict__ x,  const float* __restrict__ fb,
         const float* __restrict__ lg, const float* __restrict__ lb,
         float* __restrict__ out)
{
    extern __shared__ char smem[];
    uint32_t sb = smem_u32(smem);
    int tid = threadIdx.x, warp = tid >> 5, lane = tid & 31;
    int nw = warp & 3, mg = warp >> 2, mrow = mg * 64;
    long rowBase = (long)blockIdx.x * 128;   // grid = 1024
    int b = blockIdx.x >> 5;                 // 32 tiles per batch

    if (tid < 128) {
        *(float*)(smem + SM_BASE + tid * 4) = fb[tid] + g_agg[b * Dc + tid];
        *(float*)(smem + SM_G  + tid * 4) = lg[tid];
        *(float*)(smem + SM_B2 + tid * 4) = lb[tid];
    }

    convert_a(smem, x, nullptr, rowBase, tid);
    __syncthreads();

    float acc[4][4][4];
    #pragma unroll
    for (int i = 0; i < 4; i++)
        #pragma unroll
        for (int j = 0; j < 4; j++)
            #pragma unroll
            for (int k = 0; k < 4; k++) acc[i][j][k] = 0.f;

    warp_gemm(acc, sb, g_bff, mrow, nw, lane);

    const float* bs = (const float*)(smem + SM_BASE);
    const float* gs = (const float*)(smem + SM_G);
    const float* ts = (const float*)(smem + SM_B2);
    int cb = (lane & 3) * 2 + nw * 32;
    float gg[4][2], bb[4][2];
    #pragma unroll
    for (int nt = 0; nt < 4; nt++) {
        int c = cb + nt * 8;
        float b0 = bs[c], b1 = bs[c + 1];
        gg[nt][0] = gs[c]; gg[nt][1] = gs[c + 1];
        bb[nt][0] = ts[c]; bb[nt][1] = ts[c + 1];
        #pragma unroll
        for (int mt = 0; mt < 4; mt++) {
            acc[mt][nt][0] += b0; acc[mt][nt][1] += b1;
            acc[mt][nt][2] += b0; acc[mt][nt][3] += b1;
        }
    }

    // row stats: quad butterfly then cross-warp combine via smem
    float2* red = (float2*)(smem + SM_RED);
    int r0 = lane >> 2;
    #pragma unroll
    for (int mt = 0; mt < 4; mt++) {
        #pragma unroll
        for (int h = 0; h < 2; h++) {
            float S = 0.f, Q = 0.f;
            #pragma unroll
            for (int nt = 0; nt < 4; nt++) {
                float v0 = acc[mt][nt][2 * h], v1 = acc[mt][nt][2 * h + 1];
                S += v0 + v1; Q += v0 * v0 + v1 * v1;
            }
            S += __shfl_xor_sync(0xffffffffu, S, 1);
            Q += __shfl_xor_sync(0xffffffffu, Q, 1);
            S += __shfl_xor_sync(0xffffffffu, S, 2);
            Q += __shfl_xor_sync(0xffffffffu, Q, 2);
            if ((lane & 3) == 0)
                red[(mrow + mt * 16 + r0 + 8 * h) * 4 + nw] = make_float2(S, Q);
        }
    }
    __syncthreads();
    float2* mui = (float2*)(smem + SM_MUI);
    if (tid < 128) {
        float2 a = red[tid * 4], c1 = red[tid * 4 + 1],
               c2 = red[tid * 4 + 2], c3 = red[tid * 4 + 3];
        float Sr = a.x + c1.x + c2.x + c3.x;
        float Qr = a.y + c1.y + c2.y + c3.y;
        const float invD = 1.0f / 128.0f;
        float mu  = Sr * invD;
        float var = Qr * invD - mu * mu;
        mui[tid] = make_float2(mu, rsqrtf(var + 1e-5f));
    }
    __syncthreads();

    #pragma unroll
    for (int mt = 0; mt < 4; mt++) {
        #pragma unroll
        for (int h = 0; h < 2; h++) {
            int row = mrow + mt * 16 + r0 + 8 * h;
            float2 mi = mui[row];
            float* op = out + (rowBase + row) * Dc;
            #pragma unroll
            for (int nt = 0; nt < 4; nt++) {
                int c = cb + nt * 8;
                float o0 = (acc[mt][nt][2*h]   - mi.x) * mi.y * gg[nt][0] + bb[nt][0];
                float o1 = (acc[mt][nt][2*h+1] - mi.x) * mi.y * gg[nt][1] + bb[nt][1];
                *(float2*)&op[c] = make_float2(o0, o1);
            }
        }
    }
}

// ---------------------------------------------------------------------------
extern "C" void kernel_launch(void* const* d_in, const int* in_sizes, int n_in,
                              void* d_out, int out_size)
{
    const float* x   = (const float*)d_in[0];
    const float* sw  = (const float*)d_in[1];
    const float* sb  = (const float*)d_in[2];
    const float* spw = (const float*)d_in[3];
    const float* spb = (const float*)d_in[4];
    const float* fw  = (const float*)d_in[5];
    const float* fb  = (const float*)d_in[6];
    const float* lg  = (const float*)d_in[7];
    const float* lb  = (const float*)d_in[8];
    float* out = (float*)d_out;

    scores_kernel<<<(Bc * Lc) / 32, 256>>>(x, sw, sb, spw, fw);
    select_kernel<<<Bc, 512>>>();
    sparse_mma<<<Bc * SP_TILES, 256, SM_TOTAL>>>(x, spb);
    full_mma<<<(Bc * Lc) / 128, 256, SM_TOTAL>>>(x, fb, lg, lb, out);
}